// round 1
// baseline (speedup 1.0000x reference)
#include <cuda_runtime.h>

#define Tt 64
#define Ll 64
#define Bb 128
#define Hh 64
#define NSM 148
#define NTHR 256

// Full h history: h[t][l][b][u]  (134 MB) -- removes all WAR hazards in the wavefront.
__device__ float g_h[(size_t)Tt * Ll * Bb * Hh];
// Cell state c[l][b][u] -- single buffered (only (t,l) reads c@t-1 and then overwrites).
__device__ float g_c[(size_t)Ll * Bb * Hh];
__device__ int   g_flags[Tt * Ll];
__device__ float g_partial[Tt];

typedef unsigned long long u64;

__device__ __forceinline__ u64 pack2(float a, float b) {
    u64 r; asm("mov.b64 %0, {%1, %2};" : "=l"(r) : "f"(a), "f"(b)); return r;
}
__device__ __forceinline__ void unpack2(u64 v, float& a, float& b) {
    asm("mov.b64 {%0, %1}, %2;" : "=f"(a), "=f"(b) : "l"(v));
}
__device__ __forceinline__ void fma2(u64& acc, u64 a, u64 b) {
    asm("fma.rn.f32x2 %0, %1, %2, %0;" : "+l"(acc) : "l"(a), "l"(b));
}
__device__ __forceinline__ float sigm(float x) {
    return __fdividef(1.0f, 1.0f + __expf(-x));
}

__global__ void init_kernel() {
    int i = blockIdx.x * blockDim.x + threadIdx.x;
    if (i < Tt * Ll) g_flags[i] = 0;
}

// Persistent wavefront kernel. Work item w -> (diag d, cell (t,l), colgroup cg).
// Cell (t,l): z[128,256] = [h_in | h_prev] @ W + b, gates, update c/h.
// 2 CTAs per cell (cg = 32-unit column group). Static strided ticket order
// (diagonal-major) guarantees deadlock-free progress with 148 resident CTAs.
__global__ void __launch_bounds__(NTHR, 1) wave_kernel(
    const float* __restrict__ x,  const float* __restrict__ W0,
    const float* __restrict__ b0, const float* __restrict__ Wl,
    const float* __restrict__ bl)
{
    __shared__ float Xs[128][20];   // [row][k-chunk 16 + pad]
    __shared__ float Ws[16][132];   // [k][128 local cols + pad]

    const int tid = threadIdx.x;
    const int r0  = (tid >> 4) * 8;   // 8 batch rows per thread
    const int u0  = (tid & 15) * 2;   // 2 adjacent hidden units per thread

    for (int w = blockIdx.x; w < Tt * Ll * 2; w += gridDim.x) {
        // ---- decode ticket -> (t, l, cg), diagonal-major order ----
        int rem = w, d = 0;
        for (;; ++d) {
            int nd = min(min(d + 1, 127 - d), 64);
            if (rem < nd * 2) break;
            rem -= nd * 2;
        }
        const int cg   = rem & 1;
        const int cell = rem >> 1;
        const int t0d  = (d > 63) ? (d - 63) : 0;
        const int t    = t0d + cell;
        const int l    = d - t;

        // ---- acquire dependencies ----
        if (tid == 0) {
            if (l > 0) { volatile int* f = &g_flags[t * Ll + (l - 1)]; while (*f < 2) { } }
            if (t > 0) { volatile int* f = &g_flags[(t - 1) * Ll + l]; while (*f < 2) { } }
            __threadfence();
        }
        __syncthreads();

        const int    Keff = (l == 0) ? 65 : 128;
        const float* W    = (l == 0) ? W0 : (Wl + (size_t)(l - 1) * 128 * 256);
        const float* bias = (l == 0) ? b0 : (bl + (l - 1) * 256);

        const float* hin_base   = (l > 0) ? &g_h[((size_t)t * Ll + (l - 1)) * Bb * Hh] : (const float*)0;
        const float* hprev_base = (t > 0) ? &g_h[((size_t)(t - 1) * Ll + l) * Bb * Hh] : (const float*)0;

        // bias preload; seed accumulators with bias (pairs of adjacent units)
        u64 acc[8][4];
        {
            u64 bseed[4];
            #pragma unroll
            for (int g = 0; g < 4; g++) {
                float bA = bias[g * 64 + cg * 32 + u0];
                float bB = bias[g * 64 + cg * 32 + u0 + 1];
                bseed[g] = pack2(bA, bB);
            }
            #pragma unroll
            for (int i = 0; i < 8; i++)
                #pragma unroll
                for (int g = 0; g < 4; g++) acc[i][g] = bseed[g];
        }

        const int nch = (Keff + 15) >> 4;
        for (int kc = 0; kc < nch * 16; kc += 16) {
            // ---- stage X chunk: Xs[row][0..15] = X[row][kc..kc+15] ----
            {
                int row = tid >> 1, half = tid & 1;
                int ks = kc + half * 8;
                float4 v0, v1;
                if (l > 0) {
                    if (ks < 64) {
                        const float4* p = (const float4*)(hin_base + row * Hh + ks);
                        v0 = p[0]; v1 = p[1];
                    } else if (t > 0) {
                        const float4* p = (const float4*)(hprev_base + row * Hh + (ks - 64));
                        v0 = p[0]; v1 = p[1];
                    } else {
                        v0 = make_float4(0.f, 0.f, 0.f, 0.f); v1 = v0;
                    }
                } else {
                    // layer 0: k==0 -> x scalar, k in [1,65) -> h_prev[k-1], else 0
                    float tmp[8];
                    #pragma unroll
                    for (int q = 0; q < 8; q++) {
                        int k = ks + q; float v = 0.f;
                        if (k == 0) v = x[row * Tt + t];
                        else if (k < 65 && t > 0) v = hprev_base[row * Hh + (k - 1)];
                        tmp[q] = v;
                    }
                    v0 = make_float4(tmp[0], tmp[1], tmp[2], tmp[3]);
                    v1 = make_float4(tmp[4], tmp[5], tmp[6], tmp[7]);
                }
                *(float4*)&Xs[row][half * 8]     = v0;
                *(float4*)&Xs[row][half * 8 + 4] = v1;
            }
            // ---- stage W chunk: Ws[k][j] , j = g*32 + u (our 128 cols) ----
            {
                int k = tid >> 4, j0 = (tid & 15) * 8;
                int gk = kc + k;
                float4 v0, v1;
                if (gk < Keff) {
                    int g = j0 >> 5, uu = j0 & 31;
                    const float* p = W + (size_t)gk * 256 + g * 64 + cg * 32 + uu;
                    v0 = ((const float4*)p)[0]; v1 = ((const float4*)p)[1];
                } else {
                    v0 = make_float4(0.f, 0.f, 0.f, 0.f); v1 = v0;
                }
                *(float4*)&Ws[k][j0]     = v0;
                *(float4*)&Ws[k][j0 + 4] = v1;
            }
            __syncthreads();

            // ---- packed f32x2 outer-product: 8 rows x 4 gate-pairs per thread ----
            #pragma unroll
            for (int k = 0; k < 16; k++) {
                u64 b2[4];
                #pragma unroll
                for (int g = 0; g < 4; g++)
                    b2[g] = *(const u64*)&Ws[k][g * 32 + u0];
                #pragma unroll
                for (int i = 0; i < 8; i++) {
                    float a = Xs[r0 + i][k];
                    u64 a2 = pack2(a, a);
                    #pragma unroll
                    for (int g = 0; g < 4; g++) fma2(acc[i][g], a2, b2[g]);
                }
            }
            __syncthreads();
        }

        // ---- gates (thread-local: this thread owns i/j/f/o for its 2 units) ----
        float* cptr = &g_c[(size_t)l * Bb * Hh];
        float* hout = &g_h[((size_t)t * Ll + l) * Bb * Hh];
        #pragma unroll
        for (int i = 0; i < 8; i++) {
            int row = r0 + i;
            int off = row * Hh + cg * 32 + u0;
            float zi0, zi1, zj0, zj1, zf0, zf1, zo0, zo1;
            unpack2(acc[i][0], zi0, zi1);
            unpack2(acc[i][1], zj0, zj1);
            unpack2(acc[i][2], zf0, zf1);
            unpack2(acc[i][3], zo0, zo1);
            float cp0 = 0.f, cp1 = 0.f;
            if (t > 0) {
                float2 cp = __ldcg((const float2*)(cptr + off));
                cp0 = cp.x; cp1 = cp.y;
            }
            float c20 = cp0 * sigm(zf0) + sigm(zi0) * tanhf(zj0);
            float c21 = cp1 * sigm(zf1) + sigm(zi1) * tanhf(zj1);
            float h20 = tanhf(c20) * sigm(zo0);
            float h21 = tanhf(c21) * sigm(zo1);
            __stcg((float2*)(cptr + off), make_float2(c20, c21));
            *(float2*)(hout + off) = make_float2(h20, h21);
        }

        // ---- release ----
        __threadfence();
        __syncthreads();
        if (tid == 0) atomicAdd(&g_flags[t * Ll + l], 1);
    }
}

// pred[b,t] = relu(h[t][63][b][:] . Wd[t] + bd[t]); per-t squared-error partials.
__global__ void dense_kernel(const float* __restrict__ labels, const float* __restrict__ Wd,
                             const float* __restrict__ bd, float* __restrict__ out)
{
    int t = blockIdx.x;     // 0..63
    int b = threadIdx.x;    // 0..127
    __shared__ float wd[64];
    __shared__ float red[128];
    if (b < 64) wd[b] = Wd[t * 64 + b];
    __syncthreads();
    const float* hrow = &g_h[(((size_t)t * Ll + 63) * Bb + b) * Hh];
    float acc = 0.f;
    #pragma unroll
    for (int u = 0; u < 64; u++) acc += hrow[u] * wd[u];
    float p = acc + bd[t];
    p = (p > 0.f) ? p : 0.f;
    out[b * 64 + t] = p;
    float e = labels[b * 64 + t] - p;
    red[b] = e * e;
    __syncthreads();
    for (int s = 64; s > 0; s >>= 1) {
        if (b < s) red[b] += red[b + s];
        __syncthreads();
    }
    if (b == 0) g_partial[t] = red[0];
}

__global__ void loss_kernel(float* out, int out_size)
{
    __shared__ float red[64];
    int tid = threadIdx.x;
    red[tid] = g_partial[tid];
    __syncthreads();
    for (int s = 32; s > 0; s >>= 1) {
        if (tid < s) red[tid] += red[tid + s];
        __syncthreads();
    }
    if (tid == 0 && out_size > Bb * Tt) out[Bb * Tt] = red[0] / (float)(Bb * Tt);
}

extern "C" void kernel_launch(void* const* d_in, const int* in_sizes, int n_in,
                              void* d_out, int out_size) {
    const float* x      = (const float*)d_in[0];
    const float* labels = (const float*)d_in[1];
    const float* W0     = (const float*)d_in[2];
    const float* b0     = (const float*)d_in[3];
    const float* Wl     = (const float*)d_in[4];
    const float* bl     = (const float*)d_in[5];
    const float* Wd     = (const float*)d_in[6];
    const float* bd     = (const float*)d_in[7];
    float* out = (float*)d_out;

    init_kernel<<<16, 256>>>();
    wave_kernel<<<NSM, NTHR>>>(x, W0, b0, Wl, bl);
    dense_kernel<<<64, 128>>>(labels, Wd, bd, out);
    loss_kernel<<<1, 64>>>(out, out_size);
}

// round 2
// speedup vs baseline: 1.2358x; 1.2358x over previous
#include <cuda_runtime.h>

#define Tt 64
#define Ll 64
#define Bb 128
#define Hh 64
#define NSM 148
#define NTHR 256
#define NSPLIT 4                 // CTAs per cell (column split)
#define NTICK (Tt * Ll * NSPLIT)

// Full h history: h[t][l][b][u] (134 MB) -- removes all WAR hazards.
__device__ float g_h[(size_t)Tt * Ll * Bb * Hh];
// Cell state c[l][b][u] -- single buffered (reader==writer chain), L2-only access.
__device__ float g_c[(size_t)Ll * Bb * Hh];
__device__ int   g_flags[Tt * Ll];
__device__ float g_partial[Tt];

typedef unsigned long long u64;

__device__ __forceinline__ u64 pack2(float a, float b) {
    u64 r; asm("mov.b64 %0, {%1, %2};" : "=l"(r) : "f"(a), "f"(b)); return r;
}
__device__ __forceinline__ void unpack2(u64 v, float& a, float& b) {
    asm("mov.b64 {%0, %1}, %2;" : "=f"(a), "=f"(b) : "l"(v));
}
__device__ __forceinline__ void fma2(u64& acc, u64 a, u64 b) {
    asm("fma.rn.f32x2 %0, %1, %2, %0;" : "+l"(acc) : "l"(a), "l"(b));
}
__device__ __forceinline__ float sigm(float x) {
    return __fdividef(1.0f, 1.0f + __expf(-x));
}

__global__ void init_kernel() {
    int i = blockIdx.x * blockDim.x + threadIdx.x;
    if (i < Tt * Ll) g_flags[i] = 0;
}

// Persistent wavefront kernel. 4 CTAs per cell (cg = 16-unit column group of
// each of the 4 gates -> 64 output cols per CTA). Diagonal-major static
// strided ticket order => deadlock-free with 148 resident CTAs.
__global__ void __launch_bounds__(NTHR, 1) wave_kernel(
    const float* __restrict__ x,  const float* __restrict__ W0,
    const float* __restrict__ b0, const float* __restrict__ Wl,
    const float* __restrict__ bl)
{
    __shared__ u64   Xs2[128][17];   // X value duplicated in both f32 lanes
    __shared__ float Ws[16][68];     // [k][local col j = g*16 + u]

    const int tid = threadIdx.x;
    const int r0  = (tid >> 3) * 4;   // 4 batch rows per thread
    const int u0  = (tid & 7) * 2;    // 2 adjacent units (within 16-unit group)

    for (int w = blockIdx.x; w < NTICK; w += gridDim.x) {
        // ---- decode ticket -> (t, l, cg), diagonal-major ----
        int rem = w, d = 0;
        for (;; ++d) {
            int nd4 = min(min(d + 1, 127 - d), 64) * NSPLIT;
            if (rem < nd4) break;
            rem -= nd4;
        }
        const int cg   = rem & 3;
        const int cell = rem >> 2;
        const int t    = ((d > 63) ? (d - 63) : 0) + cell;
        const int l    = d - t;

        // ---- acquire deps ----
        if (tid == 0) {
            if (l > 0) { volatile int* f = &g_flags[t * Ll + (l - 1)]; while (*f < NSPLIT) { } }
            if (t > 0) { volatile int* f = &g_flags[(t - 1) * Ll + l]; while (*f < NSPLIT) { } }
            __threadfence();
        }
        __syncthreads();

        const int    Keff = (l == 0) ? 65 : 128;
        const float* W    = (l == 0) ? W0 : (Wl + (size_t)(l - 1) * 128 * 256);
        const float* bias = (l == 0) ? b0 : (bl + (l - 1) * 256);

        const float* hin_base   = (l > 0) ? &g_h[((size_t)t * Ll + (l - 1)) * Bb * Hh] : (const float*)0;
        const float* hprev_base = (t > 0) ? &g_h[((size_t)(t - 1) * Ll + l) * Bb * Hh] : (const float*)0;

        // seed accumulators with bias pairs: col = g*64 + cg*16 + u0
        u64 acc[4][4];
        {
            #pragma unroll
            for (int g = 0; g < 4; g++) {
                const float* bp = bias + g * 64 + cg * 16 + u0;
                u64 bs = pack2(bp[0], bp[1]);
                #pragma unroll
                for (int i = 0; i < 4; i++) acc[i][g] = bs;
            }
        }

        const int nch = (Keff + 15) >> 4;

        // staging roles
        const int xrow  = tid >> 1;        // 128 rows, 2 threads/row
        const int xhalf = tid & 1;         // which 8-k half
        const int wk    = tid >> 4;        // k within chunk
        const int wj0   = (tid & 15) * 4;  // local col start (float4)
        const int wg    = wj0 >> 4;
        const int woff  = wj0 & 15;

        float xv[8];
        float4 wv;

        // ---- prefetch chunk 0 into registers ----
        {
            int ks = 0 + xhalf * 8;
            if (l > 0) {
                const float4* p = (const float4*)(hin_base + xrow * Hh + ks);
                float4 a = p[0], b = p[1];
                xv[0]=a.x; xv[1]=a.y; xv[2]=a.z; xv[3]=a.w;
                xv[4]=b.x; xv[5]=b.y; xv[6]=b.z; xv[7]=b.w;
            } else {
                #pragma unroll
                for (int q = 0; q < 8; q++) {
                    int k = ks + q; float v = 0.f;
                    if (k == 0) v = x[xrow * Tt + t];
                    else if (t > 0) v = hprev_base[xrow * Hh + (k - 1)];
                    xv[q] = v;
                }
            }
            wv = ((const float4*)(W + (size_t)wk * 256 + wg * 64 + cg * 16 + woff))[0];
        }

        for (int c = 0; c < nch; c++) {
            __syncthreads();   // previous compute done; smem reusable
            // store staged chunk
            #pragma unroll
            for (int q = 0; q < 8; q++)
                Xs2[xrow][xhalf * 8 + q] = pack2(xv[q], xv[q]);
            *(float4*)&Ws[wk][wj0] = wv;
            __syncthreads();

            // prefetch next chunk while computing this one
            if (c + 1 < nch) {
                int kc = (c + 1) * 16;
                int ks = kc + xhalf * 8;
                if (l > 0) {
                    if (ks < 64) {
                        const float4* p = (const float4*)(hin_base + xrow * Hh + ks);
                        float4 a = p[0], b = p[1];
                        xv[0]=a.x; xv[1]=a.y; xv[2]=a.z; xv[3]=a.w;
                        xv[4]=b.x; xv[5]=b.y; xv[6]=b.z; xv[7]=b.w;
                    } else if (t > 0) {
                        const float4* p = (const float4*)(hprev_base + xrow * Hh + (ks - 64));
                        float4 a = p[0], b = p[1];
                        xv[0]=a.x; xv[1]=a.y; xv[2]=a.z; xv[3]=a.w;
                        xv[4]=b.x; xv[5]=b.y; xv[6]=b.z; xv[7]=b.w;
                    } else {
                        #pragma unroll
                        for (int q = 0; q < 8; q++) xv[q] = 0.f;
                    }
                } else {
                    #pragma unroll
                    for (int q = 0; q < 8; q++) {
                        int k = ks + q; float v = 0.f;
                        if (k < 65 && t > 0) v = hprev_base[xrow * Hh + (k - 1)];
                        xv[q] = v;
                    }
                }
                int gk = kc + wk;
                if (gk < Keff)
                    wv = ((const float4*)(W + (size_t)gk * 256 + wg * 64 + cg * 16 + woff))[0];
                else
                    wv = make_float4(0.f, 0.f, 0.f, 0.f);
            }

            // ---- packed f32x2 outer product: 4 rows x 4 gate-pairs ----
            #pragma unroll
            for (int k = 0; k < 16; k++) {
                u64 b2[4];
                #pragma unroll
                for (int g = 0; g < 4; g++)
                    b2[g] = *(const u64*)&Ws[k][g * 16 + u0];
                u64 a2[4];
                #pragma unroll
                for (int i = 0; i < 4; i++)
                    a2[i] = Xs2[r0 + i][k];
                #pragma unroll
                for (int i = 0; i < 4; i++)
                    #pragma unroll
                    for (int g = 0; g < 4; g++) fma2(acc[i][g], a2[i], b2[g]);
            }
        }

        // ---- gates: thread-local combine (owns i/j/f/o for its 2 units) ----
        float* cptr = &g_c[(size_t)l * Bb * Hh];
        float* hout = &g_h[((size_t)t * Ll + l) * Bb * Hh];
        #pragma unroll
        for (int i = 0; i < 4; i++) {
            int row = r0 + i;
            int off = row * Hh + cg * 16 + u0;
            float zi0, zi1, zj0, zj1, zf0, zf1, zo0, zo1;
            unpack2(acc[i][0], zi0, zi1);
            unpack2(acc[i][1], zj0, zj1);
            unpack2(acc[i][2], zf0, zf1);
            unpack2(acc[i][3], zo0, zo1);
            float cp0 = 0.f, cp1 = 0.f;
            if (t > 0) {
                float2 cp = __ldcg((const float2*)(cptr + off));
                cp0 = cp.x; cp1 = cp.y;
            }
            float c20 = cp0 * sigm(zf0) + sigm(zi0) * tanhf(zj0);
            float c21 = cp1 * sigm(zf1) + sigm(zi1) * tanhf(zj1);
            float h20 = tanhf(c20) * sigm(zo0);
            float h21 = tanhf(c21) * sigm(zo1);
            __stcg((float2*)(cptr + off), make_float2(c20, c21));
            *(float2*)(hout + off) = make_float2(h20, h21);
        }

        // ---- release ----
        __threadfence();
        __syncthreads();
        if (tid == 0) atomicAdd(&g_flags[t * Ll + l], 1);
    }
}

// pred[b,t] = relu(h[t][63][b][:] . Wd[t] + bd[t]); per-t squared-error partials.
__global__ void dense_kernel(const float* __restrict__ labels, const float* __restrict__ Wd,
                             const float* __restrict__ bd, float* __restrict__ out)
{
    int t = blockIdx.x;     // 0..63
    int b = threadIdx.x;    // 0..127
    __shared__ float wd[64];
    __shared__ float red[128];
    if (b < 64) wd[b] = Wd[t * 64 + b];
    __syncthreads();
    const float* hrow = &g_h[(((size_t)t * Ll + 63) * Bb + b) * Hh];
    float acc = 0.f;
    #pragma unroll
    for (int u = 0; u < 64; u++) acc += hrow[u] * wd[u];
    float p = acc + bd[t];
    p = (p > 0.f) ? p : 0.f;
    out[b * 64 + t] = p;
    float e = labels[b * 64 + t] - p;
    red[b] = e * e;
    __syncthreads();
    for (int s = 64; s > 0; s >>= 1) {
        if (b < s) red[b] += red[b + s];
        __syncthreads();
    }
    if (b == 0) g_partial[t] = red[0];
}

__global__ void loss_kernel(float* out, int out_size)
{
    __shared__ float red[64];
    int tid = threadIdx.x;
    red[tid] = g_partial[tid];
    __syncthreads();
    for (int s = 32; s > 0; s >>= 1) {
        if (tid < s) red[tid] += red[tid + s];
        __syncthreads();
    }
    if (tid == 0 && out_size > Bb * Tt) out[Bb * Tt] = red[0] / (float)(Bb * Tt);
}

extern "C" void kernel_launch(void* const* d_in, const int* in_sizes, int n_in,
                              void* d_out, int out_size) {
    const float* x      = (const float*)d_in[0];
    const float* labels = (const float*)d_in[1];
    const float* W0     = (const float*)d_in[2];
    const float* b0     = (const float*)d_in[3];
    const float* Wl     = (const float*)d_in[4];
    const float* bl     = (const float*)d_in[5];
    const float* Wd     = (const float*)d_in[6];
    const float* bd     = (const float*)d_in[7];
    float* out = (float*)d_out;

    init_kernel<<<16, 256>>>();
    wave_kernel<<<NSM, NTHR>>>(x, W0, b0, Wl, bl);
    dense_kernel<<<64, 128>>>(labels, Wd, bd, out);
    loss_kernel<<<1, 64>>>(out, out_size);
}

// round 4
// speedup vs baseline: 1.2941x; 1.0472x over previous
#include <cuda_runtime.h>

#define Tt 64
#define Ll 64
#define Bb 128
#define Hh 64
#define NSM 148
#define NTHR 256
#define NSPLIT 4                 // CTAs per cell (column split)
#define NTICK (Tt * Ll * NSPLIT)

// Full h history: h[t][l][b][u] (134 MB) -- removes all WAR hazards.
__device__ float g_h[(size_t)Tt * Ll * Bb * Hh];
// Cell state c[l][b][u] -- single buffered (reader==writer chain), L2-only access.
__device__ float g_c[(size_t)Ll * Bb * Hh];
__device__ int   g_flags[Tt * Ll];
__device__ float g_partial[Tt];

typedef unsigned long long u64;

__device__ __forceinline__ u64 pack2(float a, float b) {
    u64 r; asm("mov.b64 %0, {%1, %2};" : "=l"(r) : "f"(a), "f"(b)); return r;
}
__device__ __forceinline__ void unpack2(u64 v, float& a, float& b) {
    asm("mov.b64 {%0, %1}, %2;" : "=f"(a), "=f"(b) : "l"(v));
}
__device__ __forceinline__ void fma2(u64& acc, u64 a, u64 b) {
    asm("fma.rn.f32x2 %0, %1, %2, %0;" : "+l"(acc) : "l"(a), "l"(b));
}
__device__ __forceinline__ float sigm(float x) {
    return __fdividef(1.0f, 1.0f + __expf(-x));
}

__global__ void init_kernel() {
    int i = blockIdx.x * blockDim.x + threadIdx.x;
    if (i < Tt * Ll) g_flags[i] = 0;
}

// Persistent wavefront kernel. 4 CTAs per cell (cg = 16-unit column group of
// each of the 4 gates -> 64 output cols per CTA). Diagonal-major static
// strided ticket order => deadlock-free with 148 resident CTAs.
__global__ void __launch_bounds__(NTHR, 1) wave_kernel(
    const float* __restrict__ x,  const float* __restrict__ W0,
    const float* __restrict__ b0, const float* __restrict__ Wl,
    const float* __restrict__ bl)
{
    __shared__ u64   Xs2[128][17];   // X value duplicated in both f32 lanes
    __shared__ float Ws[16][68];     // [k][local col j = g*16 + u]

    const int tid = threadIdx.x;
    const int r0  = (tid >> 3) * 4;   // 4 batch rows per thread
    const int u0  = (tid & 7) * 2;    // 2 adjacent units (within 16-unit group)

    for (int w = blockIdx.x; w < NTICK; w += gridDim.x) {
        // ---- decode ticket -> (t, l, cg), diagonal-major ----
        int rem = w, d = 0;
        for (;; ++d) {
            int nd4 = min(min(d + 1, 127 - d), 64) * NSPLIT;
            if (rem < nd4) break;
            rem -= nd4;
        }
        const int cg   = rem & 3;
        const int cell = rem >> 2;
        const int t    = ((d > 63) ? (d - 63) : 0) + cell;
        const int l    = d - t;

        // ---- acquire deps ----
        if (tid == 0) {
            if (l > 0) { volatile int* f = &g_flags[t * Ll + (l - 1)]; while (*f < NSPLIT) { } }
            if (t > 0) { volatile int* f = &g_flags[(t - 1) * Ll + l]; while (*f < NSPLIT) { } }
            __threadfence();
        }
        __syncthreads();

        const int    Keff = (l == 0) ? 65 : 128;
        const float* W    = (l == 0) ? W0 : (Wl + (size_t)(l - 1) * 128 * 256);
        const float* bias = (l == 0) ? b0 : (bl + (l - 1) * 256);

        const float* hin_base   = (l > 0) ? &g_h[((size_t)t * Ll + (l - 1)) * Bb * Hh] : (const float*)0;
        const float* hprev_base = (t > 0) ? &g_h[((size_t)(t - 1) * Ll + l) * Bb * Hh] : (const float*)0;

        // seed accumulators with bias pairs: col = g*64 + cg*16 + u0
        u64 acc[4][4];
        {
            #pragma unroll
            for (int g = 0; g < 4; g++) {
                const float* bp = bias + g * 64 + cg * 16 + u0;
                u64 bs = pack2(bp[0], bp[1]);
                #pragma unroll
                for (int i = 0; i < 4; i++) acc[i][g] = bs;
            }
        }

        const int nch = (Keff + 15) >> 4;

        // staging roles
        const int xrow  = tid >> 1;        // 128 rows, 2 threads/row
        const int xhalf = tid & 1;         // which 8-k half
        const int wk    = tid >> 4;        // k within chunk
        const int wj0   = (tid & 15) * 4;  // local col start (float4)
        const int wg    = wj0 >> 4;
        const int woff  = wj0 & 15;

        float xv[8];
        float4 wv;

        // ---- prefetch chunk 0 into registers ----
        {
            int ks = 0 + xhalf * 8;
            if (l > 0) {
                const float4* p = (const float4*)(hin_base + xrow * Hh + ks);
                float4 a = p[0], b = p[1];
                xv[0]=a.x; xv[1]=a.y; xv[2]=a.z; xv[3]=a.w;
                xv[4]=b.x; xv[5]=b.y; xv[6]=b.z; xv[7]=b.w;
            } else {
                #pragma unroll
                for (int q = 0; q < 8; q++) {
                    int k = ks + q; float v = 0.f;
                    if (k == 0) v = x[xrow * Tt + t];
                    else if (t > 0) v = hprev_base[xrow * Hh + (k - 1)];
                    xv[q] = v;
                }
            }
            wv = ((const float4*)(W + (size_t)wk * 256 + wg * 64 + cg * 16 + woff))[0];
        }

        for (int c = 0; c < nch; c++) {
            __syncthreads();   // previous compute done; smem reusable
            // store staged chunk
            #pragma unroll
            for (int q = 0; q < 8; q++)
                Xs2[xrow][xhalf * 8 + q] = pack2(xv[q], xv[q]);
            *(float4*)&Ws[wk][wj0] = wv;
            __syncthreads();

            // prefetch next chunk while computing this one
            if (c + 1 < nch) {
                int kc = (c + 1) * 16;
                int ks = kc + xhalf * 8;
                if (l > 0) {
                    if (ks < 64) {
                        const float4* p = (const float4*)(hin_base + xrow * Hh + ks);
                        float4 a = p[0], b = p[1];
                        xv[0]=a.x; xv[1]=a.y; xv[2]=a.z; xv[3]=a.w;
                        xv[4]=b.x; xv[5]=b.y; xv[6]=b.z; xv[7]=b.w;
                    } else if (t > 0) {
                        const float4* p = (const float4*)(hprev_base + xrow * Hh + (ks - 64));
                        float4 a = p[0], b = p[1];
                        xv[0]=a.x; xv[1]=a.y; xv[2]=a.z; xv[3]=a.w;
                        xv[4]=b.x; xv[5]=b.y; xv[6]=b.z; xv[7]=b.w;
                    } else {
                        #pragma unroll
                        for (int q = 0; q < 8; q++) xv[q] = 0.f;
                    }
                } else {
                    #pragma unroll
                    for (int q = 0; q < 8; q++) {
                        int k = ks + q; float v = 0.f;
                        if (k < 65 && t > 0) v = hprev_base[xrow * Hh + (k - 1)];
                        xv[q] = v;
                    }
                }
                int gk = kc + wk;
                if (gk < Keff)
                    wv = ((const float4*)(W + (size_t)gk * 256 + wg * 64 + cg * 16 + woff))[0];
                else
                    wv = make_float4(0.f, 0.f, 0.f, 0.f);
            }

            // ---- packed f32x2 outer product: 4 rows x 4 gate-pairs ----
            #pragma unroll
            for (int k = 0; k < 16; k++) {
                u64 b2[4];
                #pragma unroll
                for (int g = 0; g < 4; g++)
                    b2[g] = *(const u64*)&Ws[k][g * 16 + u0];
                u64 a2[4];
                #pragma unroll
                for (int i = 0; i < 4; i++)
                    a2[i] = Xs2[r0 + i][k];
                #pragma unroll
                for (int i = 0; i < 4; i++)
                    #pragma unroll
                    for (int g = 0; g < 4; g++) fma2(acc[i][g], a2[i], b2[g]);
            }
        }

        // ---- gates: thread-local combine (owns i/j/f/o for its 2 units) ----
        float* cptr = &g_c[(size_t)l * Bb * Hh];
        float* hout = &g_h[((size_t)t * Ll + l) * Bb * Hh];
        #pragma unroll
        for (int i = 0; i < 4; i++) {
            int row = r0 + i;
            int off = row * Hh + cg * 16 + u0;
            float zi0, zi1, zj0, zj1, zf0, zf1, zo0, zo1;
            unpack2(acc[i][0], zi0, zi1);
            unpack2(acc[i][1], zj0, zj1);
            unpack2(acc[i][2], zf0, zf1);
            unpack2(acc[i][3], zo0, zo1);
            float cp0 = 0.f, cp1 = 0.f;
            if (t > 0) {
                float2 cp = __ldcg((const float2*)(cptr + off));
                cp0 = cp.x; cp1 = cp.y;
            }
            float c20 = cp0 * sigm(zf0) + sigm(zi0) * tanhf(zj0);
            float c21 = cp1 * sigm(zf1) + sigm(zi1) * tanhf(zj1);
            float h20 = tanhf(c20) * sigm(zo0);
            float h21 = tanhf(c21) * sigm(zo1);
            __stcg((float2*)(cptr + off), make_float2(c20, c21));
            *(float2*)(hout + off) = make_float2(h20, h21);
        }

        // ---- release ----
        __threadfence();
        __syncthreads();
        if (tid == 0) atomicAdd(&g_flags[t * Ll + l], 1);
    }
}

// pred[b,t] = relu(h[t][63][b][:] . Wd[t] + bd[t]); per-t squared-error partials.
__global__ void dense_kernel(const float* __restrict__ labels, const float* __restrict__ Wd,
                             const float* __restrict__ bd, float* __restrict__ out)
{
    int t = blockIdx.x;     // 0..63
    int b = threadIdx.x;    // 0..127
    __shared__ float wd[64];
    __shared__ float red[128];
    if (b < 64) wd[b] = Wd[t * 64 + b];
    __syncthreads();
    const float* hrow = &g_h[(((size_t)t * Ll + 63) * Bb + b) * Hh];
    float acc = 0.f;
    #pragma unroll
    for (int u = 0; u < 64; u++) acc += hrow[u] * wd[u];
    float p = acc + bd[t];
    p = (p > 0.f) ? p : 0.f;
    out[b * 64 + t] = p;
    float e = labels[b * 64 + t] - p;
    red[b] = e * e;
    __syncthreads();
    for (int s = 64; s > 0; s >>= 1) {
        if (b < s) red[b] += red[b + s];
        __syncthreads();
    }
    if (b == 0) g_partial[t] = red[0];
}

__global__ void loss_kernel(float* out, int out_size)
{
    __shared__ float red[64];
    int tid = threadIdx.x;
    red[tid] = g_partial[tid];
    __syncthreads();
    for (int s = 32; s > 0; s >>= 1) {
        if (tid < s) red[tid] += red[tid + s];
        __syncthreads();
    }
    if (tid == 0 && out_size > Bb * Tt) out[Bb * Tt] = red[0] / (float)(Bb * Tt);
}

extern "C" void kernel_launch(void* const* d_in, const int* in_sizes, int n_in,
                              void* d_out, int out_size) {
    const float* x      = (const float*)d_in[0];
    const float* labels = (const float*)d_in[1];
    const float* W0     = (const float*)d_in[2];
    const float* b0     = (const float*)d_in[3];
    const float* Wl     = (const float*)d_in[4];
    const float* bl     = (const float*)d_in[5];
    const float* Wd     = (const float*)d_in[6];
    const float* bd     = (const float*)d_in[7];
    float* out = (float*)d_out;

    init_kernel<<<16, 256>>>();
    wave_kernel<<<NSM, NTHR>>>(x, W0, b0, Wl, bl);
    dense_kernel<<<64, 128>>>(labels, Wd, bd, out);
    loss_kernel<<<1, 64>>>(out, out_size);
}